// round 2
// baseline (speedup 1.0000x reference)
#include <cuda_runtime.h>
#include <cstdint>
#include <math.h>

// Problem constants
#define NB   64     // batch
#define NT   256    // time
#define NK   5
#define NX   512
#define NH   512
#define NG   2048   // 4*H
#define NF   1024   // 2*X
#define BT   16384  // NB*NT

// ---------------- device scratch (static: no allocations allowed) ----------------
__device__ float d_xg[(size_t)BT * NF];            // 67 MB   x_g_t
__device__ float d_pre[(size_t)NT * NB * NG];      // 134 MB  pre-gates, [t][b][g]
__device__ float d_h[2][NB * NH];                  // ping-pong hidden state
__device__ float d_houts[(size_t)NT * NB * NH];    // 33.5 MB all h_t
__device__ float d_scaleArr[NT];
__device__ float d_shiftArr[NT];
__device__ unsigned d_bar_count;
__device__ unsigned d_bar_gen;

// ---------------- f32x2 packed math helpers (sm_100+) ----------------
__device__ __forceinline__ unsigned long long pack2(float lo, float hi) {
    unsigned long long r;
    asm("mov.b64 %0, {%1, %2};" : "=l"(r) : "f"(lo), "f"(hi));
    return r;
}
__device__ __forceinline__ void fma2(unsigned long long &d, unsigned long long a, unsigned long long b) {
    asm("fma.rn.f32x2 %0, %1, %2, %0;" : "+l"(d) : "l"(a), "l"(b));
}
__device__ __forceinline__ float2 unpack2(unsigned long long v) {
    float2 f;
    asm("mov.b64 {%0, %1}, %2;" : "=f"(f.x), "=f"(f.y) : "l"(v));
    return f;
}

// ---------------- kernel 1: build x_g_t = concat(x[:,:,0,:], mean(x[:,:,1:,:])) ----------------
__global__ __launch_bounds__(256) void prep_kernel(const float* __restrict__ x) {
    int idx = blockIdx.x * blockDim.x + threadIdx.x;   // one float4 of xg
    int f4 = idx & 255;
    int bt = idx >> 8;
    if (bt >= BT) return;
    int f = f4 * 4;
    const float* xb = x + (size_t)bt * (NK * NX);
    float4 v;
    if (f < NX) {
        v = *(const float4*)(xb + f);
    } else {
        int xr = f - NX;
        float4 a1 = *(const float4*)(xb + 1 * NX + xr);
        float4 a2 = *(const float4*)(xb + 2 * NX + xr);
        float4 a3 = *(const float4*)(xb + 3 * NX + xr);
        float4 a4 = *(const float4*)(xb + 4 * NX + xr);
        v.x = (a1.x + a2.x + a3.x + a4.x) * 0.25f;
        v.y = (a1.y + a2.y + a3.y + a4.y) * 0.25f;
        v.z = (a1.z + a2.z + a3.z + a4.z) * 0.25f;
        v.w = (a1.w + a2.w + a3.w + a4.w) * 0.25f;
    }
    *(float4*)&d_xg[(size_t)bt * NF + f] = v;
}

// ---------------- kernel 2: pre = xg @ W_ih^T + (b_ih + b_hh), written as [t][b][g] ----------------
// M=16384, N=2048, K=1024.  BM=BN=128, BK=16, 256 threads, 8x8 micro-tile, f32x2 packed FMA.
__global__ __launch_bounds__(256) void gemm_kernel(const float* __restrict__ Wih,
                                                   const float* __restrict__ bih,
                                                   const float* __restrict__ bhh) {
    __shared__ float As[16][132];
    __shared__ float Bs[16][132];
    const int mtile = blockIdx.y;
    const int ntile = blockIdx.x;
    const int tid = threadIdx.x;
    const int tx = tid & 15;      // n split
    const int ty = tid >> 4;      // m split
    const float* Ag = d_xg + (size_t)mtile * 128 * NF;
    const float* Bg = Wih + (size_t)ntile * 128 * NF;

    unsigned long long acc[8][4];
#pragma unroll
    for (int i = 0; i < 8; i++)
#pragma unroll
        for (int j = 0; j < 4; j++) acc[i][j] = 0ull;   // == {0.f,0.f}

    const int lrow = tid >> 2;          // 0..63
    const int lk4  = (tid & 3) * 4;     // 0,4,8,12

    for (int k0 = 0; k0 < NF; k0 += 16) {
        float4 a0 = *(const float4*)(Ag + (size_t)lrow * NF + k0 + lk4);
        float4 a1 = *(const float4*)(Ag + (size_t)(lrow + 64) * NF + k0 + lk4);
        float4 b0 = *(const float4*)(Bg + (size_t)lrow * NF + k0 + lk4);
        float4 b1 = *(const float4*)(Bg + (size_t)(lrow + 64) * NF + k0 + lk4);
        __syncthreads();
        As[lk4 + 0][lrow] = a0.x; As[lk4 + 1][lrow] = a0.y; As[lk4 + 2][lrow] = a0.z; As[lk4 + 3][lrow] = a0.w;
        As[lk4 + 0][lrow + 64] = a1.x; As[lk4 + 1][lrow + 64] = a1.y; As[lk4 + 2][lrow + 64] = a1.z; As[lk4 + 3][lrow + 64] = a1.w;
        Bs[lk4 + 0][lrow] = b0.x; Bs[lk4 + 1][lrow] = b0.y; Bs[lk4 + 2][lrow] = b0.z; Bs[lk4 + 3][lrow] = b0.w;
        Bs[lk4 + 0][lrow + 64] = b1.x; Bs[lk4 + 1][lrow + 64] = b1.y; Bs[lk4 + 2][lrow + 64] = b1.z; Bs[lk4 + 3][lrow + 64] = b1.w;
        __syncthreads();
#pragma unroll
        for (int kk = 0; kk < 16; kk++) {
            float4 m0 = *(const float4*)&As[kk][ty * 4];
            float4 m1 = *(const float4*)&As[kk][64 + ty * 4];
            float4 n0 = *(const float4*)&Bs[kk][tx * 4];
            float4 n1 = *(const float4*)&Bs[kk][64 + tx * 4];
            unsigned long long bn0 = pack2(n0.x, n0.y);
            unsigned long long bn1 = pack2(n0.z, n0.w);
            unsigned long long bn2 = pack2(n1.x, n1.y);
            unsigned long long bn3 = pack2(n1.z, n1.w);
            float mreg[8] = {m0.x, m0.y, m0.z, m0.w, m1.x, m1.y, m1.z, m1.w};
#pragma unroll
            for (int i = 0; i < 8; i++) {
                unsigned long long am = pack2(mreg[i], mreg[i]);
                fma2(acc[i][0], am, bn0);
                fma2(acc[i][1], am, bn1);
                fma2(acc[i][2], am, bn2);
                fma2(acc[i][3], am, bn3);
            }
        }
    }
    // epilogue: add bias, scatter to pre[t][b][g]
#pragma unroll
    for (int i = 0; i < 8; i++) {
        int m = mtile * 128 + ((i < 4) ? (ty * 4 + i) : (64 + ty * 4 + i - 4));
        int b = m >> 8;       // bt = b*256 + t
        int t = m & 255;
        float* outrow = d_pre + ((size_t)t * NB + b) * NG;
#pragma unroll
        for (int j = 0; j < 4; j++) {
            int n = ntile * 128 + ((j < 2) ? (tx * 4 + 2 * j) : (64 + tx * 4 + 2 * (j - 2)));
            float2 v = unpack2(acc[i][j]);
            float2 o;
            o.x = v.x + bih[n] + bhh[n];
            o.y = v.y + bih[n + 1] + bhh[n + 1];
            *(float2*)&outrow[n] = o;
        }
    }
}

// ---------------- persistent scan kernel: 128 CTAs, custom grid barrier ----------------
__device__ __forceinline__ void grid_barrier(unsigned nb) {
    __threadfence();
    __syncthreads();
    if (threadIdx.x == 0) {
        unsigned my = *(volatile unsigned*)&d_bar_gen;
        if (atomicAdd(&d_bar_count, 1u) == nb - 1u) {
            d_bar_count = 0u;
            __threadfence();
            *(volatile unsigned*)&d_bar_gen = my + 1u;
        } else {
            while (*(volatile unsigned*)&d_bar_gen == my) { }
        }
        __threadfence();
    }
    __syncthreads();
}

// CTA (hg,bg): hg in 0..31 -> 16 h-columns, bg in 0..3 -> 16 batches.
// W_hh slice (64 gate-rows x 512) lives in smem for all 256 steps.
// Per-cell c-state lives in a register.
__global__ __launch_bounds__(256) void scan_kernel(const float* __restrict__ Whh) {
    extern __shared__ float sm[];
    float* Ws   = sm;                       // 64 * 513
    float* hs   = sm + 64 * 513;            // 512 * 20 (padded)
    float* zbuf = hs + 512 * 20;            // 64 * 17

    const int tid = threadIdx.x;
    const int cid = blockIdx.x;
    const int hg = cid & 31;
    const int bg = cid >> 5;

    // load W_hh slice into smem (rows: gate q, colsub cs -> global row q*512 + hg*16 + cs)
    for (int idx = tid; idx < 64 * 512; idx += 256) {
        int r = idx >> 9, k = idx & 511;
        int q = r >> 4, cs = r & 15;
        int G = q * NH + hg * 16 + cs;
        Ws[r * 513 + k] = Whh[(size_t)G * NH + k];
    }

    // cell ownership for gate phase
    const int colsub = tid & 15;
    const int bsub = tid >> 4;
    const int col = hg * 16 + colsub;
    const int bb = bg * 16 + bsub;
    d_h[0][bb * NH + col] = 0.f;     // init h
    float c = 0.f;                   // init c (register-resident)

    // matmul-phase mapping
    const int r = tid & 63;
    const int bq = tid >> 6;                // 4 batch quads
    const float* wrow = Ws + r * 513;
    const int q = r >> 4, cs2 = r & 15;
    const int G = q * NH + hg * 16 + cs2;
    const float* hp = hs + bq * 4;

    grid_barrier(gridDim.x);   // h zeros visible everywhere; Ws loaded (via the internal syncthreads)

    for (int t = 0; t < NT; t++) {
        // stage h_{t-1}[bslice][:] into smem
        const float* hb = d_h[t & 1];
        for (int idx = tid; idx < 16 * 512; idx += 256) {
            int sb = idx >> 9, k = idx & 511;
            hs[k * 20 + sb] = hb[(bg * 16 + sb) * NH + k];
        }
        __syncthreads();

        // z[r][bq*4..+3] = dot(Ws[r], h[b])  (f32x2 packed, 4 outputs/thread)
        unsigned long long acc01 = 0ull, acc23 = 0ull;
#pragma unroll 4
        for (int k = 0; k < 512; k++) {
            float w = wrow[k];
            ulonglong2 hh = *(const ulonglong2*)(hp + k * 20);   // {h0,h1},{h2,h3} broadcast
            unsigned long long w2 = pack2(w, w);
            fma2(acc01, w2, hh.x);
            fma2(acc23, w2, hh.y);
        }
        const float* prow = d_pre + ((size_t)t * NB + bg * 16 + bq * 4) * NG + G;
        float2 z01 = unpack2(acc01);
        float2 z23 = unpack2(acc23);
        zbuf[r * 17 + bq * 4 + 0] = z01.x + prow[0 * NG];
        zbuf[r * 17 + bq * 4 + 1] = z01.y + prow[1 * NG];
        zbuf[r * 17 + bq * 4 + 2] = z23.x + prow[2 * NG];
        zbuf[r * 17 + bq * 4 + 3] = z23.y + prow[3 * NG];
        __syncthreads();

        // gates + state update for this thread's cell
        float zi = zbuf[(0 * 16 + colsub) * 17 + bsub];
        float zf = zbuf[(1 * 16 + colsub) * 17 + bsub];
        float zg = zbuf[(2 * 16 + colsub) * 17 + bsub];
        float zo = zbuf[(3 * 16 + colsub) * 17 + bsub];
        float ig = 1.f / (1.f + expf(-zi));
        float fg = 1.f / (1.f + expf(-zf));
        float gg = tanhf(zg);
        float og = 1.f / (1.f + expf(-zo));
        c = fg * c + ig * gg;
        float hv = og * tanhf(c);
        d_h[(t + 1) & 1][bb * NH + col] = hv;
        d_houts[(size_t)t * (NB * NH) + bb * NH + col] = hv;

        grid_barrier(gridDim.x);
    }
}

// ---------------- kernel 4: per-t BN stats -> scale/shift ----------------
__global__ __launch_bounds__(256) void stats_kernel(const float* __restrict__ gamma,
                                                    const float* __restrict__ beta) {
    int t = blockIdx.x;
    const float4* p = (const float4*)(d_houts + (size_t)t * (NB * NH));
    float s = 0.f, ss = 0.f;
    for (int i = threadIdx.x; i < (NB * NH) / 4; i += 256) {
        float4 v = p[i];
        s  += v.x + v.y + v.z + v.w;
        ss += v.x * v.x + v.y * v.y + v.z * v.z + v.w * v.w;
    }
#pragma unroll
    for (int o = 16; o > 0; o >>= 1) {
        s  += __shfl_down_sync(0xffffffffu, s, o);
        ss += __shfl_down_sync(0xffffffffu, ss, o);
    }
    __shared__ float rs[8], rss[8];
    int w = threadIdx.x >> 5;
    if ((threadIdx.x & 31) == 0) { rs[w] = s; rss[w] = ss; }
    __syncthreads();
    if (threadIdx.x == 0) {
        float S = 0.f, SS = 0.f;
#pragma unroll
        for (int i = 0; i < 8; i++) { S += rs[i]; SS += rss[i]; }
        float mean = S * (1.f / (NB * NH));
        float var = SS * (1.f / (NB * NH)) - mean * mean;
        float sc = gamma[t] * rsqrtf(var + 1e-5f);
        d_scaleArr[t] = sc;
        d_shiftArr[t] = beta[t] - mean * sc;
    }
}

// ---------------- kernel 5: elu(BN(h)) mean over t -> out[b][h] ----------------
__global__ __launch_bounds__(256) void final_kernel(float* __restrict__ out) {
    int idx = blockIdx.x * 256 + threadIdx.x;   // b*512 + h
    float acc = 0.f;
#pragma unroll 4
    for (int t = 0; t < NT; t++) {
        float v = d_houts[(size_t)t * (NB * NH) + idx];
        float u = v * d_scaleArr[t] + d_shiftArr[t];
        acc += (u > 0.f) ? u : expm1f(u);
    }
    out[idx] = acc * (1.f / NT);
}

// ---------------- launch ----------------
extern "C" void kernel_launch(void* const* d_in, const int* in_sizes, int n_in,
                              void* d_out, int out_size) {
    const float* x     = (const float*)d_in[0];
    const float* Wih   = (const float*)d_in[1];
    const float* Whh   = (const float*)d_in[2];
    const float* bih   = (const float*)d_in[3];
    const float* bhh   = (const float*)d_in[4];
    const float* gamma = (const float*)d_in[5];
    const float* beta  = (const float*)d_in[6];
    float* out = (float*)d_out;

    prep_kernel<<<BT, 256>>>(x);

    dim3 ggrid(NG / 128, BT / 128);
    gemm_kernel<<<ggrid, 256>>>(Wih, bih, bhh);

    int smem = (64 * 513 + 512 * 20 + 64 * 17) * (int)sizeof(float);   // 176,640 B
    cudaFuncSetAttribute(scan_kernel, cudaFuncAttributeMaxDynamicSharedMemorySize, smem);
    scan_kernel<<<128, 256, smem>>>(Whh);

    stats_kernel<<<NT, 256>>>(gamma, beta);
    final_kernel<<<(NB * NH) / 256, 256>>>(out);
}